// round 7
// baseline (speedup 1.0000x reference)
#include <cuda_runtime.h>
#include <cuda_bf16.h>
#include <cstdint>

#define Bsz 65536
#define Dd  256
#define Ee  16

// ---------------- scratch (device globals; no allocation allowed) ----------
__device__ float g_h[(size_t)Bsz * Dd];        // router hidden, 64 MB
__device__ float g_prob[Bsz * 2];              // top-2 softmax probs
__device__ int   g_list[2][Ee * Bsz];          // per-slot, per-expert token lists
__device__ int   g_cnt[32];                    // [slot*16 + e]

__device__ __forceinline__ uint32_t f2tf32(float f) {
    uint32_t u;
    asm("cvt.rna.tf32.f32 %0, %1;" : "=r"(u) : "f"(f));
    return u;
}
__device__ __forceinline__ float lrelu(float v) { return v > 0.f ? v : 0.01f * v; }

__device__ __forceinline__ void mma_tf32(float c[4], const uint32_t a[4], const uint32_t b[2]) {
    asm volatile(
        "mma.sync.aligned.m16n8k8.row.col.f32.tf32.tf32.f32 "
        "{%0,%1,%2,%3},{%4,%5,%6,%7},{%8,%9},{%0,%1,%2,%3};"
        : "+f"(c[0]), "+f"(c[1]), "+f"(c[2]), "+f"(c[3])
        : "r"(a[0]), "r"(a[1]), "r"(a[2]), "r"(a[3]), "r"(b[0]), "r"(b[1]));
}
__device__ __forceinline__ void mma_bf16(float c[4], const uint32_t a[4], const uint32_t b[2]) {
    asm volatile(
        "mma.sync.aligned.m16n8k16.row.col.f32.bf16.bf16.f32 "
        "{%0,%1,%2,%3},{%4,%5,%6,%7},{%8,%9},{%0,%1,%2,%3};"
        : "+f"(c[0]), "+f"(c[1]), "+f"(c[2]), "+f"(c[3])
        : "r"(a[0]), "r"(a[1]), "r"(a[2]), "r"(a[3]), "r"(b[0]), "r"(b[1]));
}

// pack two floats into bf16x2 (e0 -> low half = even k, e1 -> high half)
__device__ __forceinline__ uint32_t pk_bf16(float e0, float e1) {
    uint32_t r;
    asm("cvt.rn.bf16x2.f32 %0, %1, %2;" : "=r"(r) : "f"(e1), "f"(e0));
    return r;
}

__global__ void zero_cnt_kernel() {
    if (threadIdx.x < 32) g_cnt[threadIdx.x] = 0;
}

// ===========================================================================
// GEMM1 (router hidden): tf32x3, CTA 128x128, BK=32.  h = lrelu(x@Wr1^T+br1)
// (unchanged from the passing Round-2 kernel except MMA pass de-interleaving)
// ===========================================================================
#define SROW 36
#define TILE_U32 (128 * SROW)
#define SMEM1_BYTES (4 * TILE_U32 * 4)

__global__ void __launch_bounds__(256, 2)
gemm1_tf32x3_kernel(const float* __restrict__ A,
                    const float* __restrict__ Wg,
                    const float* __restrict__ bias)
{
    extern __shared__ uint32_t dsm[];
    uint32_t* sAhi = dsm;
    uint32_t* sAlo = dsm + TILE_U32;
    uint32_t* sBhi = dsm + 2 * TILE_U32;
    uint32_t* sBlo = dsm + 3 * TILE_U32;

    const int t  = threadIdx.x;
    const int bm = blockIdx.x;
    const int bn = blockIdx.y;

    float acc[4][4][4];
#pragma unroll
    for (int mt = 0; mt < 4; mt++)
#pragma unroll
        for (int nt = 0; nt < 4; nt++)
#pragma unroll
            for (int i = 0; i < 4; i++) acc[mt][nt][i] = 0.f;

    const int warp = t >> 5, lane = t & 31;
    const int wm = (warp & 1) * 64;
    const int wn = (warp >> 1) * 32;
    const int g  = lane >> 2;
    const int tg = lane & 3;

    const int lr = t >> 3;
    const int lc = (t & 7) * 4;

#pragma unroll 1
    for (int kt = 0; kt < 8; kt++) {
        const int k0 = kt * 32;
#pragma unroll
        for (int rr = 0; rr < 128; rr += 32) {
            const int r = rr + lr;
            float4 v = *(const float4*)(A + (size_t)(bm * 128 + r) * Dd + k0 + lc);
            uint32_t hx = f2tf32(v.x), hy = f2tf32(v.y), hz = f2tf32(v.z), hw = f2tf32(v.w);
            sAhi[r * SROW + lc + 0] = hx;  sAhi[r * SROW + lc + 1] = hy;
            sAhi[r * SROW + lc + 2] = hz;  sAhi[r * SROW + lc + 3] = hw;
            sAlo[r * SROW + lc + 0] = f2tf32(v.x - __uint_as_float(hx));
            sAlo[r * SROW + lc + 1] = f2tf32(v.y - __uint_as_float(hy));
            sAlo[r * SROW + lc + 2] = f2tf32(v.z - __uint_as_float(hz));
            sAlo[r * SROW + lc + 3] = f2tf32(v.w - __uint_as_float(hw));
            float4 w = *(const float4*)(Wg + (size_t)(bn * 128 + r) * Dd + k0 + lc);
            uint32_t gx = f2tf32(w.x), gy = f2tf32(w.y), gz = f2tf32(w.z), gw = f2tf32(w.w);
            sBhi[r * SROW + lc + 0] = gx;  sBhi[r * SROW + lc + 1] = gy;
            sBhi[r * SROW + lc + 2] = gz;  sBhi[r * SROW + lc + 3] = gw;
            sBlo[r * SROW + lc + 0] = f2tf32(w.x - __uint_as_float(gx));
            sBlo[r * SROW + lc + 1] = f2tf32(w.y - __uint_as_float(gy));
            sBlo[r * SROW + lc + 2] = f2tf32(w.z - __uint_as_float(gz));
            sBlo[r * SROW + lc + 3] = f2tf32(w.w - __uint_as_float(gw));
        }
        __syncthreads();

#pragma unroll
        for (int ks = 0; ks < 4; ks++) {
            const int kb = ks * 8;
            uint32_t af[4][4], bh[4][2], bl[4][2];
#pragma unroll
            for (int nt = 0; nt < 4; nt++) {
                const int n0 = (wn + nt * 8 + g) * SROW;
                bh[nt][0] = sBhi[n0 + kb + tg];
                bh[nt][1] = sBhi[n0 + kb + tg + 4];
                bl[nt][0] = sBlo[n0 + kb + tg];
                bl[nt][1] = sBlo[n0 + kb + tg + 4];
            }
#pragma unroll
            for (int mt = 0; mt < 4; mt++) {
                const int r0 = (wm + mt * 16 + g) * SROW;
                af[mt][0] = sAhi[r0 + kb + tg];
                af[mt][1] = sAhi[r0 + 8 * SROW + kb + tg];
                af[mt][2] = sAhi[r0 + kb + tg + 4];
                af[mt][3] = sAhi[r0 + 8 * SROW + kb + tg + 4];
            }
            // three independent 16-wide sweeps (no same-acc back-to-back)
#pragma unroll
            for (int mt = 0; mt < 4; mt++)
#pragma unroll
                for (int nt = 0; nt < 4; nt++) mma_tf32(acc[mt][nt], af[mt], bh[nt]);
#pragma unroll
            for (int mt = 0; mt < 4; mt++)
#pragma unroll
                for (int nt = 0; nt < 4; nt++) mma_tf32(acc[mt][nt], af[mt], bl[nt]);
#pragma unroll
            for (int mt = 0; mt < 4; mt++) {
                const int r0 = (wm + mt * 16 + g) * SROW;
                af[mt][0] = sAlo[r0 + kb + tg];
                af[mt][1] = sAlo[r0 + 8 * SROW + kb + tg];
                af[mt][2] = sAlo[r0 + kb + tg + 4];
                af[mt][3] = sAlo[r0 + 8 * SROW + kb + tg + 4];
            }
#pragma unroll
            for (int mt = 0; mt < 4; mt++)
#pragma unroll
                for (int nt = 0; nt < 4; nt++) mma_tf32(acc[mt][nt], af[mt], bh[nt]);
        }
        __syncthreads();
    }

#pragma unroll
    for (int mt = 0; mt < 4; mt++) {
        const int rbase = wm + mt * 16 + g;
#pragma unroll
        for (int nt = 0; nt < 4; nt++) {
            const int gc = bn * 128 + wn + nt * 8 + tg * 2;
            const float b0v = bias[gc], b1v = bias[gc + 1];
#pragma unroll
            for (int hh = 0; hh < 2; hh++) {
                const int r = rbase + hh * 8;
                const size_t gr = (size_t)(bm * 128 + r) * Dd;
                g_h[gr + gc]     = lrelu(acc[mt][nt][hh * 2 + 0] + b0v);
                g_h[gr + gc + 1] = lrelu(acc[mt][nt][hh * 2 + 1] + b1v);
            }
        }
    }
}

// ===========================================================================
// Expert GEMMs: bf16x3 (hi/lo bf16 split), CTA 128x128, BK=64, m16n8k16.
// MODE 1: rows from g_list[0][e], out = p0*(acc+be[e])
// MODE 2: rows from g_list[1][e], out = lrelu(out + p1*(acc+be[e]))
// u32-packed bf16 pairs: fragment indexing identical to tf32 kernel.
// ===========================================================================
#define BROW 36                        // 32 kk + 4 pad (u32)
#define BTILE (128 * BROW)             // one 128x64 tile (u32 pairs)
#define SMEM2_BYTES (4 * BTILE * 4 + 128 * 4 + 128 * 4)

template <int MODE>
__global__ void __launch_bounds__(256, 2)
gemm_bf16x3_kernel(const float* __restrict__ A,
                   const float* __restrict__ Wg,
                   const float* __restrict__ bias,
                   float* __restrict__ out)
{
    extern __shared__ uint32_t dsm[];
    uint32_t* sAhi = dsm;
    uint32_t* sAlo = dsm + BTILE;
    uint32_t* sBhi = dsm + 2 * BTILE;
    uint32_t* sBlo = dsm + 3 * BTILE;
    int*      sTok = (int*)(dsm + 4 * BTILE);
    float*    sP   = (float*)(sTok + 128);

    const int t  = threadIdx.x;
    const int bm = blockIdx.x;
    const int bn = blockIdx.y;
    const int e    = blockIdx.z;
    const int slot = MODE - 1;

    const int count = g_cnt[slot * 16 + e];
    if (bm * 128 >= count) return;              // uniform early exit, before any sync
    const float* W    = Wg + (size_t)e * Dd * Dd;
    const float* bvec = bias + e * Dd;

    if (t < 128) {
        int item = bm * 128 + t;
        int tok = 0; float p = 0.f;
        if (item < count) {
            tok = g_list[slot][e * Bsz + item];
            p   = g_prob[tok * 2 + slot];
        }
        sTok[t] = tok;
        sP[t]   = p;
    }
    __syncthreads();

    float acc[4][4][4];
#pragma unroll
    for (int mt = 0; mt < 4; mt++)
#pragma unroll
        for (int nt = 0; nt < 4; nt++)
#pragma unroll
            for (int i = 0; i < 4; i++) acc[mt][nt][i] = 0.f;

    const int warp = t >> 5, lane = t & 31;
    const int wm = (warp & 1) * 64;
    const int wn = (warp >> 1) * 32;
    const int g  = lane >> 2;
    const int tg = lane & 3;

#pragma unroll 1
    for (int kt = 0; kt < 4; kt++) {
        const int k0 = kt * 64;
        // ---- stage: 8 float4 slots each for A and B -> bf16 hi/lo pairs ----
#pragma unroll
        for (int i = 0; i < 8; i++) {
            const int idx = t + 256 * i;        // 0..2047
            const int r   = idx >> 4;           // 0..127
            const int c4  = (idx & 15) * 4;     // fp32 col in BK=64
            const int so  = r * BROW + (c4 >> 1);

            float4 v = *(const float4*)(A + (size_t)sTok[r] * Dd + k0 + c4);
            __nv_bfloat162 h01 = __floats2bfloat162_rn(v.x, v.y);
            __nv_bfloat162 h23 = __floats2bfloat162_rn(v.z, v.w);
            float2 f01 = __bfloat1622float2(h01);
            float2 f23 = __bfloat1622float2(h23);
            sAhi[so]     = *(const uint32_t*)&h01;
            sAhi[so + 1] = *(const uint32_t*)&h23;
            sAlo[so]     = pk_bf16(v.x - f01.x, v.y - f01.y);
            sAlo[so + 1] = pk_bf16(v.z - f23.x, v.w - f23.y);

            float4 w = *(const float4*)(W + (size_t)(bn * 128 + r) * Dd + k0 + c4);
            __nv_bfloat162 g01 = __floats2bfloat162_rn(w.x, w.y);
            __nv_bfloat162 g23 = __floats2bfloat162_rn(w.z, w.w);
            float2 e01 = __bfloat1622float2(g01);
            float2 e23 = __bfloat1622float2(g23);
            sBhi[so]     = *(const uint32_t*)&g01;
            sBhi[so + 1] = *(const uint32_t*)&g23;
            sBlo[so]     = pk_bf16(w.x - e01.x, w.y - e01.y);
            sBlo[so + 1] = pk_bf16(w.z - e23.x, w.w - e23.y);
        }
        __syncthreads();

#pragma unroll
        for (int ks = 0; ks < 4; ks++) {        // 4 k16-steps per BK=64
            const int kb = ks * 8;
            uint32_t af[4][4], bh[4][2], bl[4][2];
#pragma unroll
            for (int nt = 0; nt < 4; nt++) {
                const int n0 = (wn + nt * 8 + g) * BROW;
                bh[nt][0] = sBhi[n0 + kb + tg];
                bh[nt][1] = sBhi[n0 + kb + tg + 4];
                bl[nt][0] = sBlo[n0 + kb + tg];
                bl[nt][1] = sBlo[n0 + kb + tg + 4];
            }
#pragma unroll
            for (int mt = 0; mt < 4; mt++) {
                const int r0 = (wm + mt * 16 + g) * BROW;
                af[mt][0] = sAhi[r0 + kb + tg];
                af[mt][1] = sAhi[r0 + 8 * BROW + kb + tg];
                af[mt][2] = sAhi[r0 + kb + tg + 4];
                af[mt][3] = sAhi[r0 + 8 * BROW + kb + tg + 4];
            }
#pragma unroll
            for (int mt = 0; mt < 4; mt++)
#pragma unroll
                for (int nt = 0; nt < 4; nt++) mma_bf16(acc[mt][nt], af[mt], bh[nt]);
#pragma unroll
            for (int mt = 0; mt < 4; mt++)
#pragma unroll
                for (int nt = 0; nt < 4; nt++) mma_bf16(acc[mt][nt], af[mt], bl[nt]);
#pragma unroll
            for (int mt = 0; mt < 4; mt++) {
                const int r0 = (wm + mt * 16 + g) * BROW;
                af[mt][0] = sAlo[r0 + kb + tg];
                af[mt][1] = sAlo[r0 + 8 * BROW + kb + tg];
                af[mt][2] = sAlo[r0 + kb + tg + 4];
                af[mt][3] = sAlo[r0 + 8 * BROW + kb + tg + 4];
            }
#pragma unroll
            for (int mt = 0; mt < 4; mt++)
#pragma unroll
                for (int nt = 0; nt < 4; nt++) mma_bf16(acc[mt][nt], af[mt], bh[nt]);
        }
        __syncthreads();
    }

    // ---- epilogue ----
#pragma unroll
    for (int mt = 0; mt < 4; mt++) {
        const int rbase = wm + mt * 16 + g;
#pragma unroll
        for (int nt = 0; nt < 4; nt++) {
            const int gc = bn * 128 + wn + nt * 8 + tg * 2;
            const float b0v = bvec[gc], b1v = bvec[gc + 1];
#pragma unroll
            for (int hh = 0; hh < 2; hh++) {
                const int r    = rbase + hh * 8;
                const int item = bm * 128 + r;
                if (item < count) {
                    const float p = sP[r];
                    const size_t o = (size_t)sTok[r] * Dd + gc;
                    const float v0 = acc[mt][nt][hh * 2 + 0] + b0v;
                    const float v1 = acc[mt][nt][hh * 2 + 1] + b1v;
                    if (MODE == 1) {
                        out[o]     = p * v0;
                        out[o + 1] = p * v1;
                    } else {
                        out[o]     = lrelu(out[o]     + p * v0);
                        out[o + 1] = lrelu(out[o + 1] + p * v1);
                    }
                }
            }
        }
    }
}

// ---------------------------------------------------------------------------
// Router stage 2: logits = h @ Wr2^T + br2 ; top-2 ; softmax ; bin tokens.
// ---------------------------------------------------------------------------
__global__ void __launch_bounds__(256)
router_topk_kernel(const float* __restrict__ Wr2, const float* __restrict__ br2)
{
    __shared__ float sW[Ee * Dd];
    const int t = threadIdx.x;
#pragma unroll
    for (int i = t; i < Ee * Dd; i += 256) sW[i] = Wr2[i];
    __syncthreads();

    const int warp = t >> 5, lane = t & 31;
    const int tok = blockIdx.x * 8 + warp;

    float hv[8];
#pragma unroll
    for (int j = 0; j < 8; j++) hv[j] = g_h[(size_t)tok * Dd + j * 32 + lane];

    float lg[Ee];
#pragma unroll
    for (int e = 0; e < Ee; e++) {
        float s = 0.f;
#pragma unroll
        for (int j = 0; j < 8; j++) s += hv[j] * sW[e * Dd + j * 32 + lane];
#pragma unroll
        for (int o = 16; o; o >>= 1) s += __shfl_xor_sync(0xffffffffu, s, o);
        lg[e] = s;
    }

    if (lane == 0) {
        float v0 = -1e30f, v1 = -1e30f;
        int   i0 = 0, i1 = 0;
#pragma unroll
        for (int e = 0; e < Ee; e++) {
            const float v = lg[e] + br2[e];
            if (v > v0)      { v1 = v0; i1 = i0; v0 = v; i0 = e; }
            else if (v > v1) { v1 = v;  i1 = e; }
        }
        const float e1  = __expf(v1 - v0);
        const float inv = 1.f / (1.f + e1);
        g_prob[tok * 2 + 0] = inv;
        g_prob[tok * 2 + 1] = e1 * inv;
        const int p0 = atomicAdd(&g_cnt[i0], 1);
        g_list[0][i0 * Bsz + p0] = tok;
        const int p1 = atomicAdd(&g_cnt[16 + i1], 1);
        g_list[1][i1 * Bsz + p1] = tok;
    }
}

// ---------------------------------------------------------------------------
extern "C" void kernel_launch(void* const* d_in, const int* in_sizes, int n_in,
                              void* d_out, int out_size)
{
    (void)in_sizes; (void)n_in; (void)out_size;
    const float* x   = (const float*)d_in[0];
    const float* Wr1 = (const float*)d_in[1];
    const float* br1 = (const float*)d_in[2];
    const float* Wr2 = (const float*)d_in[3];
    const float* br2 = (const float*)d_in[4];
    const float* We  = (const float*)d_in[5];
    const float* be  = (const float*)d_in[6];
    float* out = (float*)d_out;

    static bool attr_done = false;
    if (!attr_done) {
        cudaFuncSetAttribute(gemm1_tf32x3_kernel,
                             cudaFuncAttributeMaxDynamicSharedMemorySize, SMEM1_BYTES);
        cudaFuncSetAttribute(gemm_bf16x3_kernel<1>,
                             cudaFuncAttributeMaxDynamicSharedMemorySize, SMEM2_BYTES);
        cudaFuncSetAttribute(gemm_bf16x3_kernel<2>,
                             cudaFuncAttributeMaxDynamicSharedMemorySize, SMEM2_BYTES);
        attr_done = true;
    }

    zero_cnt_kernel<<<1, 32>>>();

    // GEMM1: h = lrelu(x @ Wr1^T + br1)   (tf32x3: router flips need this)
    gemm1_tf32x3_kernel<<<dim3(Bsz / 128, Dd / 128, 1), 256, SMEM1_BYTES>>>(x, Wr1, br1);

    // Router stage 2 + top-2 + softmax + expert binning
    router_topk_kernel<<<Bsz / 8, 256>>>(Wr2, br2);

    // Expert pass, slot 0: out = p0 * (We[e0] @ x + be[e0])   (bf16x3)
    gemm_bf16x3_kernel<1><<<dim3(Bsz / 128, Dd / 128, Ee), 256, SMEM2_BYTES>>>(x, We, be, out);

    // Expert pass, slot 1: out = lrelu(out + p1 * (We[e1] @ x + be[e1]))   (bf16x3)
    gemm_bf16x3_kernel<2><<<dim3(Bsz / 128, Dd / 128, Ee), 256, SMEM2_BYTES>>>(x, We, be, out);
}

// round 8
// speedup vs baseline: 1.0109x; 1.0109x over previous
#include <cuda_runtime.h>
#include <cuda_bf16.h>
#include <cstdint>

#define Bsz 65536
#define Dd  256
#define Ee  16

// ---------------- scratch (device globals; no allocation allowed) ----------
__device__ float g_h[(size_t)Bsz * Dd];        // router hidden, 64 MB
__device__ float g_prob[Bsz * 2];              // top-2 softmax probs
__device__ int   g_list[2][Ee * Bsz];          // per-slot, per-expert token lists
__device__ int   g_cnt[32];                    // [slot*16 + e]

__device__ __forceinline__ uint32_t f2tf32(float f) {
    uint32_t u;
    asm("cvt.rna.tf32.f32 %0, %1;" : "=r"(u) : "f"(f));
    return u;
}
__device__ __forceinline__ float lrelu(float v) { return v > 0.f ? v : 0.01f * v; }

__device__ __forceinline__ void mma_tf32(float c[4], const uint32_t a[4], const uint32_t b[2]) {
    asm volatile(
        "mma.sync.aligned.m16n8k8.row.col.f32.tf32.tf32.f32 "
        "{%0,%1,%2,%3},{%4,%5,%6,%7},{%8,%9},{%0,%1,%2,%3};"
        : "+f"(c[0]), "+f"(c[1]), "+f"(c[2]), "+f"(c[3])
        : "r"(a[0]), "r"(a[1]), "r"(a[2]), "r"(a[3]), "r"(b[0]), "r"(b[1]));
}
__device__ __forceinline__ void mma_bf16(float c[4], const uint32_t a[4], const uint32_t b[2]) {
    asm volatile(
        "mma.sync.aligned.m16n8k16.row.col.f32.bf16.bf16.f32 "
        "{%0,%1,%2,%3},{%4,%5,%6,%7},{%8,%9},{%0,%1,%2,%3};"
        : "+f"(c[0]), "+f"(c[1]), "+f"(c[2]), "+f"(c[3])
        : "r"(a[0]), "r"(a[1]), "r"(a[2]), "r"(a[3]), "r"(b[0]), "r"(b[1]));
}

// pack two floats into bf16x2 (e0 -> low half = even k, e1 -> high half)
__device__ __forceinline__ uint32_t pk_bf16(float e0, float e1) {
    uint32_t r;
    asm("cvt.rn.bf16x2.f32 %0, %1, %2;" : "=r"(r) : "f"(e1), "f"(e0));
    return r;
}

__global__ void zero_cnt_kernel() {
    if (threadIdx.x < 32) g_cnt[threadIdx.x] = 0;
}

// ===========================================================================
// GEMM1 (router hidden): tf32x3, CTA 128x128, BK=32.  h = lrelu(x@Wr1^T+br1)
// (unchanged from the passing Round-2 kernel except MMA pass de-interleaving)
// ===========================================================================
#define SROW 36
#define TILE_U32 (128 * SROW)
#define SMEM1_BYTES (4 * TILE_U32 * 4)

__global__ void __launch_bounds__(256, 2)
gemm1_tf32x3_kernel(const float* __restrict__ A,
                    const float* __restrict__ Wg,
                    const float* __restrict__ bias)
{
    extern __shared__ uint32_t dsm[];
    uint32_t* sAhi = dsm;
    uint32_t* sAlo = dsm + TILE_U32;
    uint32_t* sBhi = dsm + 2 * TILE_U32;
    uint32_t* sBlo = dsm + 3 * TILE_U32;

    const int t  = threadIdx.x;
    const int bm = blockIdx.x;
    const int bn = blockIdx.y;

    float acc[4][4][4];
#pragma unroll
    for (int mt = 0; mt < 4; mt++)
#pragma unroll
        for (int nt = 0; nt < 4; nt++)
#pragma unroll
            for (int i = 0; i < 4; i++) acc[mt][nt][i] = 0.f;

    const int warp = t >> 5, lane = t & 31;
    const int wm = (warp & 1) * 64;
    const int wn = (warp >> 1) * 32;
    const int g  = lane >> 2;
    const int tg = lane & 3;

    const int lr = t >> 3;
    const int lc = (t & 7) * 4;

#pragma unroll 1
    for (int kt = 0; kt < 8; kt++) {
        const int k0 = kt * 32;
#pragma unroll
        for (int rr = 0; rr < 128; rr += 32) {
            const int r = rr + lr;
            float4 v = *(const float4*)(A + (size_t)(bm * 128 + r) * Dd + k0 + lc);
            uint32_t hx = f2tf32(v.x), hy = f2tf32(v.y), hz = f2tf32(v.z), hw = f2tf32(v.w);
            sAhi[r * SROW + lc + 0] = hx;  sAhi[r * SROW + lc + 1] = hy;
            sAhi[r * SROW + lc + 2] = hz;  sAhi[r * SROW + lc + 3] = hw;
            sAlo[r * SROW + lc + 0] = f2tf32(v.x - __uint_as_float(hx));
            sAlo[r * SROW + lc + 1] = f2tf32(v.y - __uint_as_float(hy));
            sAlo[r * SROW + lc + 2] = f2tf32(v.z - __uint_as_float(hz));
            sAlo[r * SROW + lc + 3] = f2tf32(v.w - __uint_as_float(hw));
            float4 w = *(const float4*)(Wg + (size_t)(bn * 128 + r) * Dd + k0 + lc);
            uint32_t gx = f2tf32(w.x), gy = f2tf32(w.y), gz = f2tf32(w.z), gw = f2tf32(w.w);
            sBhi[r * SROW + lc + 0] = gx;  sBhi[r * SROW + lc + 1] = gy;
            sBhi[r * SROW + lc + 2] = gz;  sBhi[r * SROW + lc + 3] = gw;
            sBlo[r * SROW + lc + 0] = f2tf32(w.x - __uint_as_float(gx));
            sBlo[r * SROW + lc + 1] = f2tf32(w.y - __uint_as_float(gy));
            sBlo[r * SROW + lc + 2] = f2tf32(w.z - __uint_as_float(gz));
            sBlo[r * SROW + lc + 3] = f2tf32(w.w - __uint_as_float(gw));
        }
        __syncthreads();

#pragma unroll
        for (int ks = 0; ks < 4; ks++) {
            const int kb = ks * 8;
            uint32_t af[4][4], bh[4][2], bl[4][2];
#pragma unroll
            for (int nt = 0; nt < 4; nt++) {
                const int n0 = (wn + nt * 8 + g) * SROW;
                bh[nt][0] = sBhi[n0 + kb + tg];
                bh[nt][1] = sBhi[n0 + kb + tg + 4];
                bl[nt][0] = sBlo[n0 + kb + tg];
                bl[nt][1] = sBlo[n0 + kb + tg + 4];
            }
#pragma unroll
            for (int mt = 0; mt < 4; mt++) {
                const int r0 = (wm + mt * 16 + g) * SROW;
                af[mt][0] = sAhi[r0 + kb + tg];
                af[mt][1] = sAhi[r0 + 8 * SROW + kb + tg];
                af[mt][2] = sAhi[r0 + kb + tg + 4];
                af[mt][3] = sAhi[r0 + 8 * SROW + kb + tg + 4];
            }
            // three independent 16-wide sweeps (no same-acc back-to-back)
#pragma unroll
            for (int mt = 0; mt < 4; mt++)
#pragma unroll
                for (int nt = 0; nt < 4; nt++) mma_tf32(acc[mt][nt], af[mt], bh[nt]);
#pragma unroll
            for (int mt = 0; mt < 4; mt++)
#pragma unroll
                for (int nt = 0; nt < 4; nt++) mma_tf32(acc[mt][nt], af[mt], bl[nt]);
#pragma unroll
            for (int mt = 0; mt < 4; mt++) {
                const int r0 = (wm + mt * 16 + g) * SROW;
                af[mt][0] = sAlo[r0 + kb + tg];
                af[mt][1] = sAlo[r0 + 8 * SROW + kb + tg];
                af[mt][2] = sAlo[r0 + kb + tg + 4];
                af[mt][3] = sAlo[r0 + 8 * SROW + kb + tg + 4];
            }
#pragma unroll
            for (int mt = 0; mt < 4; mt++)
#pragma unroll
                for (int nt = 0; nt < 4; nt++) mma_tf32(acc[mt][nt], af[mt], bh[nt]);
        }
        __syncthreads();
    }

#pragma unroll
    for (int mt = 0; mt < 4; mt++) {
        const int rbase = wm + mt * 16 + g;
#pragma unroll
        for (int nt = 0; nt < 4; nt++) {
            const int gc = bn * 128 + wn + nt * 8 + tg * 2;
            const float b0v = bias[gc], b1v = bias[gc + 1];
#pragma unroll
            for (int hh = 0; hh < 2; hh++) {
                const int r = rbase + hh * 8;
                const size_t gr = (size_t)(bm * 128 + r) * Dd;
                g_h[gr + gc]     = lrelu(acc[mt][nt][hh * 2 + 0] + b0v);
                g_h[gr + gc + 1] = lrelu(acc[mt][nt][hh * 2 + 1] + b1v);
            }
        }
    }
}

// ===========================================================================
// Expert GEMMs: bf16x3 (hi/lo bf16 split), CTA 128x128, BK=64, m16n8k16.
// MODE 1: rows from g_list[0][e], out = p0*(acc+be[e])
// MODE 2: rows from g_list[1][e], out = lrelu(out + p1*(acc+be[e]))
// u32-packed bf16 pairs: fragment indexing identical to tf32 kernel.
// ===========================================================================
#define BROW 36                        // 32 kk + 4 pad (u32)
#define BTILE (128 * BROW)             // one 128x64 tile (u32 pairs)
#define SMEM2_BYTES (4 * BTILE * 4 + 128 * 4 + 128 * 4)

template <int MODE>
__global__ void __launch_bounds__(256, 2)
gemm_bf16x3_kernel(const float* __restrict__ A,
                   const float* __restrict__ Wg,
                   const float* __restrict__ bias,
                   float* __restrict__ out)
{
    extern __shared__ uint32_t dsm[];
    uint32_t* sAhi = dsm;
    uint32_t* sAlo = dsm + BTILE;
    uint32_t* sBhi = dsm + 2 * BTILE;
    uint32_t* sBlo = dsm + 3 * BTILE;
    int*      sTok = (int*)(dsm + 4 * BTILE);
    float*    sP   = (float*)(sTok + 128);

    const int t  = threadIdx.x;
    const int bm = blockIdx.x;
    const int bn = blockIdx.y;
    const int e    = blockIdx.z;
    const int slot = MODE - 1;

    const int count = g_cnt[slot * 16 + e];
    if (bm * 128 >= count) return;              // uniform early exit, before any sync
    const float* W    = Wg + (size_t)e * Dd * Dd;
    const float* bvec = bias + e * Dd;

    if (t < 128) {
        int item = bm * 128 + t;
        int tok = 0; float p = 0.f;
        if (item < count) {
            tok = g_list[slot][e * Bsz + item];
            p   = g_prob[tok * 2 + slot];
        }
        sTok[t] = tok;
        sP[t]   = p;
    }
    __syncthreads();

    float acc[4][4][4];
#pragma unroll
    for (int mt = 0; mt < 4; mt++)
#pragma unroll
        for (int nt = 0; nt < 4; nt++)
#pragma unroll
            for (int i = 0; i < 4; i++) acc[mt][nt][i] = 0.f;

    const int warp = t >> 5, lane = t & 31;
    const int wm = (warp & 1) * 64;
    const int wn = (warp >> 1) * 32;
    const int g  = lane >> 2;
    const int tg = lane & 3;

#pragma unroll 1
    for (int kt = 0; kt < 4; kt++) {
        const int k0 = kt * 64;
        // ---- stage: 8 float4 slots each for A and B -> bf16 hi/lo pairs ----
#pragma unroll
        for (int i = 0; i < 8; i++) {
            const int idx = t + 256 * i;        // 0..2047
            const int r   = idx >> 4;           // 0..127
            const int c4  = (idx & 15) * 4;     // fp32 col in BK=64
            const int so  = r * BROW + (c4 >> 1);

            float4 v = *(const float4*)(A + (size_t)sTok[r] * Dd + k0 + c4);
            __nv_bfloat162 h01 = __floats2bfloat162_rn(v.x, v.y);
            __nv_bfloat162 h23 = __floats2bfloat162_rn(v.z, v.w);
            float2 f01 = __bfloat1622float2(h01);
            float2 f23 = __bfloat1622float2(h23);
            sAhi[so]     = *(const uint32_t*)&h01;
            sAhi[so + 1] = *(const uint32_t*)&h23;
            sAlo[so]     = pk_bf16(v.x - f01.x, v.y - f01.y);
            sAlo[so + 1] = pk_bf16(v.z - f23.x, v.w - f23.y);

            float4 w = *(const float4*)(W + (size_t)(bn * 128 + r) * Dd + k0 + c4);
            __nv_bfloat162 g01 = __floats2bfloat162_rn(w.x, w.y);
            __nv_bfloat162 g23 = __floats2bfloat162_rn(w.z, w.w);
            float2 e01 = __bfloat1622float2(g01);
            float2 e23 = __bfloat1622float2(g23);
            sBhi[so]     = *(const uint32_t*)&g01;
            sBhi[so + 1] = *(const uint32_t*)&g23;
            sBlo[so]     = pk_bf16(w.x - e01.x, w.y - e01.y);
            sBlo[so + 1] = pk_bf16(w.z - e23.x, w.w - e23.y);
        }
        __syncthreads();

#pragma unroll
        for (int ks = 0; ks < 4; ks++) {        // 4 k16-steps per BK=64
            const int kb = ks * 8;
            uint32_t af[4][4], bh[4][2], bl[4][2];
#pragma unroll
            for (int nt = 0; nt < 4; nt++) {
                const int n0 = (wn + nt * 8 + g) * BROW;
                bh[nt][0] = sBhi[n0 + kb + tg];
                bh[nt][1] = sBhi[n0 + kb + tg + 4];
                bl[nt][0] = sBlo[n0 + kb + tg];
                bl[nt][1] = sBlo[n0 + kb + tg + 4];
            }
#pragma unroll
            for (int mt = 0; mt < 4; mt++) {
                const int r0 = (wm + mt * 16 + g) * BROW;
                af[mt][0] = sAhi[r0 + kb + tg];
                af[mt][1] = sAhi[r0 + 8 * BROW + kb + tg];
                af[mt][2] = sAhi[r0 + kb + tg + 4];
                af[mt][3] = sAhi[r0 + 8 * BROW + kb + tg + 4];
            }
#pragma unroll
            for (int mt = 0; mt < 4; mt++)
#pragma unroll
                for (int nt = 0; nt < 4; nt++) mma_bf16(acc[mt][nt], af[mt], bh[nt]);
#pragma unroll
            for (int mt = 0; mt < 4; mt++)
#pragma unroll
                for (int nt = 0; nt < 4; nt++) mma_bf16(acc[mt][nt], af[mt], bl[nt]);
#pragma unroll
            for (int mt = 0; mt < 4; mt++) {
                const int r0 = (wm + mt * 16 + g) * BROW;
                af[mt][0] = sAlo[r0 + kb + tg];
                af[mt][1] = sAlo[r0 + 8 * BROW + kb + tg];
                af[mt][2] = sAlo[r0 + kb + tg + 4];
                af[mt][3] = sAlo[r0 + 8 * BROW + kb + tg + 4];
            }
#pragma unroll
            for (int mt = 0; mt < 4; mt++)
#pragma unroll
                for (int nt = 0; nt < 4; nt++) mma_bf16(acc[mt][nt], af[mt], bh[nt]);
        }
        __syncthreads();
    }

    // ---- epilogue ----
#pragma unroll
    for (int mt = 0; mt < 4; mt++) {
        const int rbase = wm + mt * 16 + g;
#pragma unroll
        for (int nt = 0; nt < 4; nt++) {
            const int gc = bn * 128 + wn + nt * 8 + tg * 2;
            const float b0v = bvec[gc], b1v = bvec[gc + 1];
#pragma unroll
            for (int hh = 0; hh < 2; hh++) {
                const int r    = rbase + hh * 8;
                const int item = bm * 128 + r;
                if (item < count) {
                    const float p = sP[r];
                    const size_t o = (size_t)sTok[r] * Dd + gc;
                    const float v0 = acc[mt][nt][hh * 2 + 0] + b0v;
                    const float v1 = acc[mt][nt][hh * 2 + 1] + b1v;
                    if (MODE == 1) {
                        out[o]     = p * v0;
                        out[o + 1] = p * v1;
                    } else {
                        out[o]     = lrelu(out[o]     + p * v0);
                        out[o + 1] = lrelu(out[o + 1] + p * v1);
                    }
                }
            }
        }
    }
}

// ---------------------------------------------------------------------------
// Router stage 2: logits = h @ Wr2^T + br2 ; top-2 ; softmax ; bin tokens.
// ---------------------------------------------------------------------------
__global__ void __launch_bounds__(256)
router_topk_kernel(const float* __restrict__ Wr2, const float* __restrict__ br2)
{
    __shared__ float sW[Ee * Dd];
    const int t = threadIdx.x;
#pragma unroll
    for (int i = t; i < Ee * Dd; i += 256) sW[i] = Wr2[i];
    __syncthreads();

    const int warp = t >> 5, lane = t & 31;
    const int tok = blockIdx.x * 8 + warp;

    float hv[8];
#pragma unroll
    for (int j = 0; j < 8; j++) hv[j] = g_h[(size_t)tok * Dd + j * 32 + lane];

    float lg[Ee];
#pragma unroll
    for (int e = 0; e < Ee; e++) {
        float s = 0.f;
#pragma unroll
        for (int j = 0; j < 8; j++) s += hv[j] * sW[e * Dd + j * 32 + lane];
#pragma unroll
        for (int o = 16; o; o >>= 1) s += __shfl_xor_sync(0xffffffffu, s, o);
        lg[e] = s;
    }

    if (lane == 0) {
        float v0 = -1e30f, v1 = -1e30f;
        int   i0 = 0, i1 = 0;
#pragma unroll
        for (int e = 0; e < Ee; e++) {
            const float v = lg[e] + br2[e];
            if (v > v0)      { v1 = v0; i1 = i0; v0 = v; i0 = e; }
            else if (v > v1) { v1 = v;  i1 = e; }
        }
        const float e1  = __expf(v1 - v0);
        const float inv = 1.f / (1.f + e1);
        g_prob[tok * 2 + 0] = inv;
        g_prob[tok * 2 + 1] = e1 * inv;
        const int p0 = atomicAdd(&g_cnt[i0], 1);
        g_list[0][i0 * Bsz + p0] = tok;
        const int p1 = atomicAdd(&g_cnt[16 + i1], 1);
        g_list[1][i1 * Bsz + p1] = tok;
    }
}

// ---------------------------------------------------------------------------
extern "C" void kernel_launch(void* const* d_in, const int* in_sizes, int n_in,
                              void* d_out, int out_size)
{
    (void)in_sizes; (void)n_in; (void)out_size;
    const float* x   = (const float*)d_in[0];
    const float* Wr1 = (const float*)d_in[1];
    const float* br1 = (const float*)d_in[2];
    const float* Wr2 = (const float*)d_in[3];
    const float* br2 = (const float*)d_in[4];
    const float* We  = (const float*)d_in[5];
    const float* be  = (const float*)d_in[6];
    float* out = (float*)d_out;

    static bool attr_done = false;
    if (!attr_done) {
        cudaFuncSetAttribute(gemm1_tf32x3_kernel,
                             cudaFuncAttributeMaxDynamicSharedMemorySize, SMEM1_BYTES);
        cudaFuncSetAttribute(gemm_bf16x3_kernel<1>,
                             cudaFuncAttributeMaxDynamicSharedMemorySize, SMEM2_BYTES);
        cudaFuncSetAttribute(gemm_bf16x3_kernel<2>,
                             cudaFuncAttributeMaxDynamicSharedMemorySize, SMEM2_BYTES);
        attr_done = true;
    }

    zero_cnt_kernel<<<1, 32>>>();

    // GEMM1: h = lrelu(x @ Wr1^T + br1)   (tf32x3: router flips need this)
    gemm1_tf32x3_kernel<<<dim3(Bsz / 128, Dd / 128, 1), 256, SMEM1_BYTES>>>(x, Wr1, br1);

    // Router stage 2 + top-2 + softmax + expert binning
    router_topk_kernel<<<Bsz / 8, 256>>>(Wr2, br2);

    // Expert pass, slot 0: out = p0 * (We[e0] @ x + be[e0])   (bf16x3)
    gemm_bf16x3_kernel<1><<<dim3(Bsz / 128, Dd / 128, Ee), 256, SMEM2_BYTES>>>(x, We, be, out);

    // Expert pass, slot 1: out = lrelu(out + p1 * (We[e1] @ x + be[e1]))   (bf16x3)
    gemm_bf16x3_kernel<2><<<dim3(Bsz / 128, Dd / 128, Ee), 256, SMEM2_BYTES>>>(x, We, be, out);
}

// round 9
// speedup vs baseline: 1.0131x; 1.0021x over previous
#include <cuda_runtime.h>
#include <cuda_bf16.h>
#include <cstdint>

#define Bsz 65536
#define Dd  256
#define Ee  16

// ---------------- scratch (device globals; no allocation allowed) ----------
__device__ float g_h[(size_t)Bsz * Dd];        // router hidden, 64 MB
__device__ float g_prob[Bsz * 2];              // top-2 softmax probs
__device__ int   g_list[2][Ee * Bsz];          // per-slot, per-expert token lists
__device__ int   g_cnt[32];                    // [slot*16 + e]

__device__ __forceinline__ uint32_t f2tf32(float f) {
    uint32_t u;
    asm("cvt.rna.tf32.f32 %0, %1;" : "=r"(u) : "f"(f));
    return u;
}
__device__ __forceinline__ float lrelu(float v) { return v > 0.f ? v : 0.01f * v; }

__device__ __forceinline__ void mma_tf32(float c[4], const uint32_t a[4], const uint32_t b[2]) {
    asm volatile(
        "mma.sync.aligned.m16n8k8.row.col.f32.tf32.tf32.f32 "
        "{%0,%1,%2,%3},{%4,%5,%6,%7},{%8,%9},{%0,%1,%2,%3};"
        : "+f"(c[0]), "+f"(c[1]), "+f"(c[2]), "+f"(c[3])
        : "r"(a[0]), "r"(a[1]), "r"(a[2]), "r"(a[3]), "r"(b[0]), "r"(b[1]));
}
__device__ __forceinline__ void mma_bf16(float c[4], const uint32_t a[4], const uint32_t b[2]) {
    asm volatile(
        "mma.sync.aligned.m16n8k16.row.col.f32.bf16.bf16.f32 "
        "{%0,%1,%2,%3},{%4,%5,%6,%7},{%8,%9},{%0,%1,%2,%3};"
        : "+f"(c[0]), "+f"(c[1]), "+f"(c[2]), "+f"(c[3])
        : "r"(a[0]), "r"(a[1]), "r"(a[2]), "r"(a[3]), "r"(b[0]), "r"(b[1]));
}

// pack two floats into bf16x2 (e0 -> low half = even k, e1 -> high half)
__device__ __forceinline__ uint32_t pk_bf16(float e0, float e1) {
    uint32_t r;
    asm("cvt.rn.bf16x2.f32 %0, %1, %2;" : "=r"(r) : "f"(e1), "f"(e0));
    return r;
}

__global__ void zero_cnt_kernel() {
    if (threadIdx.x < 32) g_cnt[threadIdx.x] = 0;
}

// ===========================================================================
// GEMM1 (router hidden): tf32x3, CTA 128x128, BK=32.  h = lrelu(x@Wr1^T+br1)
// (unchanged from the passing Round-2 kernel except MMA pass de-interleaving)
// ===========================================================================
#define SROW 36
#define TILE_U32 (128 * SROW)
#define SMEM1_BYTES (4 * TILE_U32 * 4)

__global__ void __launch_bounds__(256, 2)
gemm1_tf32x3_kernel(const float* __restrict__ A,
                    const float* __restrict__ Wg,
                    const float* __restrict__ bias)
{
    extern __shared__ uint32_t dsm[];
    uint32_t* sAhi = dsm;
    uint32_t* sAlo = dsm + TILE_U32;
    uint32_t* sBhi = dsm + 2 * TILE_U32;
    uint32_t* sBlo = dsm + 3 * TILE_U32;

    const int t  = threadIdx.x;
    const int bm = blockIdx.x;
    const int bn = blockIdx.y;

    float acc[4][4][4];
#pragma unroll
    for (int mt = 0; mt < 4; mt++)
#pragma unroll
        for (int nt = 0; nt < 4; nt++)
#pragma unroll
            for (int i = 0; i < 4; i++) acc[mt][nt][i] = 0.f;

    const int warp = t >> 5, lane = t & 31;
    const int wm = (warp & 1) * 64;
    const int wn = (warp >> 1) * 32;
    const int g  = lane >> 2;
    const int tg = lane & 3;

    const int lr = t >> 3;
    const int lc = (t & 7) * 4;

#pragma unroll 1
    for (int kt = 0; kt < 8; kt++) {
        const int k0 = kt * 32;
#pragma unroll
        for (int rr = 0; rr < 128; rr += 32) {
            const int r = rr + lr;
            float4 v = *(const float4*)(A + (size_t)(bm * 128 + r) * Dd + k0 + lc);
            uint32_t hx = f2tf32(v.x), hy = f2tf32(v.y), hz = f2tf32(v.z), hw = f2tf32(v.w);
            sAhi[r * SROW + lc + 0] = hx;  sAhi[r * SROW + lc + 1] = hy;
            sAhi[r * SROW + lc + 2] = hz;  sAhi[r * SROW + lc + 3] = hw;
            sAlo[r * SROW + lc + 0] = f2tf32(v.x - __uint_as_float(hx));
            sAlo[r * SROW + lc + 1] = f2tf32(v.y - __uint_as_float(hy));
            sAlo[r * SROW + lc + 2] = f2tf32(v.z - __uint_as_float(hz));
            sAlo[r * SROW + lc + 3] = f2tf32(v.w - __uint_as_float(hw));
            float4 w = *(const float4*)(Wg + (size_t)(bn * 128 + r) * Dd + k0 + lc);
            uint32_t gx = f2tf32(w.x), gy = f2tf32(w.y), gz = f2tf32(w.z), gw = f2tf32(w.w);
            sBhi[r * SROW + lc + 0] = gx;  sBhi[r * SROW + lc + 1] = gy;
            sBhi[r * SROW + lc + 2] = gz;  sBhi[r * SROW + lc + 3] = gw;
            sBlo[r * SROW + lc + 0] = f2tf32(w.x - __uint_as_float(gx));
            sBlo[r * SROW + lc + 1] = f2tf32(w.y - __uint_as_float(gy));
            sBlo[r * SROW + lc + 2] = f2tf32(w.z - __uint_as_float(gz));
            sBlo[r * SROW + lc + 3] = f2tf32(w.w - __uint_as_float(gw));
        }
        __syncthreads();

#pragma unroll
        for (int ks = 0; ks < 4; ks++) {
            const int kb = ks * 8;
            uint32_t af[4][4], bh[4][2], bl[4][2];
#pragma unroll
            for (int nt = 0; nt < 4; nt++) {
                const int n0 = (wn + nt * 8 + g) * SROW;
                bh[nt][0] = sBhi[n0 + kb + tg];
                bh[nt][1] = sBhi[n0 + kb + tg + 4];
                bl[nt][0] = sBlo[n0 + kb + tg];
                bl[nt][1] = sBlo[n0 + kb + tg + 4];
            }
#pragma unroll
            for (int mt = 0; mt < 4; mt++) {
                const int r0 = (wm + mt * 16 + g) * SROW;
                af[mt][0] = sAhi[r0 + kb + tg];
                af[mt][1] = sAhi[r0 + 8 * SROW + kb + tg];
                af[mt][2] = sAhi[r0 + kb + tg + 4];
                af[mt][3] = sAhi[r0 + 8 * SROW + kb + tg + 4];
            }
            // three independent 16-wide sweeps (no same-acc back-to-back)
#pragma unroll
            for (int mt = 0; mt < 4; mt++)
#pragma unroll
                for (int nt = 0; nt < 4; nt++) mma_tf32(acc[mt][nt], af[mt], bh[nt]);
#pragma unroll
            for (int mt = 0; mt < 4; mt++)
#pragma unroll
                for (int nt = 0; nt < 4; nt++) mma_tf32(acc[mt][nt], af[mt], bl[nt]);
#pragma unroll
            for (int mt = 0; mt < 4; mt++) {
                const int r0 = (wm + mt * 16 + g) * SROW;
                af[mt][0] = sAlo[r0 + kb + tg];
                af[mt][1] = sAlo[r0 + 8 * SROW + kb + tg];
                af[mt][2] = sAlo[r0 + kb + tg + 4];
                af[mt][3] = sAlo[r0 + 8 * SROW + kb + tg + 4];
            }
#pragma unroll
            for (int mt = 0; mt < 4; mt++)
#pragma unroll
                for (int nt = 0; nt < 4; nt++) mma_tf32(acc[mt][nt], af[mt], bh[nt]);
        }
        __syncthreads();
    }

#pragma unroll
    for (int mt = 0; mt < 4; mt++) {
        const int rbase = wm + mt * 16 + g;
#pragma unroll
        for (int nt = 0; nt < 4; nt++) {
            const int gc = bn * 128 + wn + nt * 8 + tg * 2;
            const float b0v = bias[gc], b1v = bias[gc + 1];
#pragma unroll
            for (int hh = 0; hh < 2; hh++) {
                const int r = rbase + hh * 8;
                const size_t gr = (size_t)(bm * 128 + r) * Dd;
                g_h[gr + gc]     = lrelu(acc[mt][nt][hh * 2 + 0] + b0v);
                g_h[gr + gc + 1] = lrelu(acc[mt][nt][hh * 2 + 1] + b1v);
            }
        }
    }
}

// ===========================================================================
// Expert GEMMs: bf16x3 (hi/lo bf16 split), CTA 128x128, BK=64, m16n8k16.
// MODE 1: rows from g_list[0][e], out = p0*(acc+be[e])
// MODE 2: rows from g_list[1][e], out = lrelu(out + p1*(acc+be[e]))
// u32-packed bf16 pairs: fragment indexing identical to tf32 kernel.
// ===========================================================================
#define BROW 36                        // 32 kk + 4 pad (u32)
#define BTILE (128 * BROW)             // one 128x64 tile (u32 pairs)
#define SMEM2_BYTES (4 * BTILE * 4 + 128 * 4 + 128 * 4)

template <int MODE>
__global__ void __launch_bounds__(256, 2)
gemm_bf16x3_kernel(const float* __restrict__ A,
                   const float* __restrict__ Wg,
                   const float* __restrict__ bias,
                   float* __restrict__ out)
{
    extern __shared__ uint32_t dsm[];
    uint32_t* sAhi = dsm;
    uint32_t* sAlo = dsm + BTILE;
    uint32_t* sBhi = dsm + 2 * BTILE;
    uint32_t* sBlo = dsm + 3 * BTILE;
    int*      sTok = (int*)(dsm + 4 * BTILE);
    float*    sP   = (float*)(sTok + 128);

    const int t  = threadIdx.x;
    const int bm = blockIdx.x;
    const int bn = blockIdx.y;
    const int e    = blockIdx.z;
    const int slot = MODE - 1;

    const int count = g_cnt[slot * 16 + e];
    if (bm * 128 >= count) return;              // uniform early exit, before any sync
    const float* W    = Wg + (size_t)e * Dd * Dd;
    const float* bvec = bias + e * Dd;

    if (t < 128) {
        int item = bm * 128 + t;
        int tok = 0; float p = 0.f;
        if (item < count) {
            tok = g_list[slot][e * Bsz + item];
            p   = g_prob[tok * 2 + slot];
        }
        sTok[t] = tok;
        sP[t]   = p;
    }
    __syncthreads();

    float acc[4][4][4];
#pragma unroll
    for (int mt = 0; mt < 4; mt++)
#pragma unroll
        for (int nt = 0; nt < 4; nt++)
#pragma unroll
            for (int i = 0; i < 4; i++) acc[mt][nt][i] = 0.f;

    const int warp = t >> 5, lane = t & 31;
    const int wm = (warp & 1) * 64;
    const int wn = (warp >> 1) * 32;
    const int g  = lane >> 2;
    const int tg = lane & 3;

#pragma unroll 1
    for (int kt = 0; kt < 4; kt++) {
        const int k0 = kt * 64;
        // ---- stage: 8 float4 slots each for A and B -> bf16 hi/lo pairs ----
#pragma unroll
        for (int i = 0; i < 8; i++) {
            const int idx = t + 256 * i;        // 0..2047
            const int r   = idx >> 4;           // 0..127
            const int c4  = (idx & 15) * 4;     // fp32 col in BK=64
            const int so  = r * BROW + (c4 >> 1);

            float4 v = *(const float4*)(A + (size_t)sTok[r] * Dd + k0 + c4);
            __nv_bfloat162 h01 = __floats2bfloat162_rn(v.x, v.y);
            __nv_bfloat162 h23 = __floats2bfloat162_rn(v.z, v.w);
            float2 f01 = __bfloat1622float2(h01);
            float2 f23 = __bfloat1622float2(h23);
            sAhi[so]     = *(const uint32_t*)&h01;
            sAhi[so + 1] = *(const uint32_t*)&h23;
            sAlo[so]     = pk_bf16(v.x - f01.x, v.y - f01.y);
            sAlo[so + 1] = pk_bf16(v.z - f23.x, v.w - f23.y);

            float4 w = *(const float4*)(W + (size_t)(bn * 128 + r) * Dd + k0 + c4);
            __nv_bfloat162 g01 = __floats2bfloat162_rn(w.x, w.y);
            __nv_bfloat162 g23 = __floats2bfloat162_rn(w.z, w.w);
            float2 e01 = __bfloat1622float2(g01);
            float2 e23 = __bfloat1622float2(g23);
            sBhi[so]     = *(const uint32_t*)&g01;
            sBhi[so + 1] = *(const uint32_t*)&g23;
            sBlo[so]     = pk_bf16(w.x - e01.x, w.y - e01.y);
            sBlo[so + 1] = pk_bf16(w.z - e23.x, w.w - e23.y);
        }
        __syncthreads();

#pragma unroll
        for (int ks = 0; ks < 4; ks++) {        // 4 k16-steps per BK=64
            const int kb = ks * 8;
            uint32_t af[4][4], bh[4][2], bl[4][2];
#pragma unroll
            for (int nt = 0; nt < 4; nt++) {
                const int n0 = (wn + nt * 8 + g) * BROW;
                bh[nt][0] = sBhi[n0 + kb + tg];
                bh[nt][1] = sBhi[n0 + kb + tg + 4];
                bl[nt][0] = sBlo[n0 + kb + tg];
                bl[nt][1] = sBlo[n0 + kb + tg + 4];
            }
#pragma unroll
            for (int mt = 0; mt < 4; mt++) {
                const int r0 = (wm + mt * 16 + g) * BROW;
                af[mt][0] = sAhi[r0 + kb + tg];
                af[mt][1] = sAhi[r0 + 8 * BROW + kb + tg];
                af[mt][2] = sAhi[r0 + kb + tg + 4];
                af[mt][3] = sAhi[r0 + 8 * BROW + kb + tg + 4];
            }
#pragma unroll
            for (int mt = 0; mt < 4; mt++)
#pragma unroll
                for (int nt = 0; nt < 4; nt++) mma_bf16(acc[mt][nt], af[mt], bh[nt]);
#pragma unroll
            for (int mt = 0; mt < 4; mt++)
#pragma unroll
                for (int nt = 0; nt < 4; nt++) mma_bf16(acc[mt][nt], af[mt], bl[nt]);
#pragma unroll
            for (int mt = 0; mt < 4; mt++) {
                const int r0 = (wm + mt * 16 + g) * BROW;
                af[mt][0] = sAlo[r0 + kb + tg];
                af[mt][1] = sAlo[r0 + 8 * BROW + kb + tg];
                af[mt][2] = sAlo[r0 + kb + tg + 4];
                af[mt][3] = sAlo[r0 + 8 * BROW + kb + tg + 4];
            }
#pragma unroll
            for (int mt = 0; mt < 4; mt++)
#pragma unroll
                for (int nt = 0; nt < 4; nt++) mma_bf16(acc[mt][nt], af[mt], bh[nt]);
        }
        __syncthreads();
    }

    // ---- epilogue ----
#pragma unroll
    for (int mt = 0; mt < 4; mt++) {
        const int rbase = wm + mt * 16 + g;
#pragma unroll
        for (int nt = 0; nt < 4; nt++) {
            const int gc = bn * 128 + wn + nt * 8 + tg * 2;
            const float b0v = bvec[gc], b1v = bvec[gc + 1];
#pragma unroll
            for (int hh = 0; hh < 2; hh++) {
                const int r    = rbase + hh * 8;
                const int item = bm * 128 + r;
                if (item < count) {
                    const float p = sP[r];
                    const size_t o = (size_t)sTok[r] * Dd + gc;
                    const float v0 = acc[mt][nt][hh * 2 + 0] + b0v;
                    const float v1 = acc[mt][nt][hh * 2 + 1] + b1v;
                    if (MODE == 1) {
                        out[o]     = p * v0;
                        out[o + 1] = p * v1;
                    } else {
                        out[o]     = lrelu(out[o]     + p * v0);
                        out[o + 1] = lrelu(out[o + 1] + p * v1);
                    }
                }
            }
        }
    }
}

// ---------------------------------------------------------------------------
// Router stage 2: logits = h @ Wr2^T + br2 ; top-2 ; softmax ; bin tokens.
// ---------------------------------------------------------------------------
__global__ void __launch_bounds__(256)
router_topk_kernel(const float* __restrict__ Wr2, const float* __restrict__ br2)
{
    __shared__ float sW[Ee * Dd];
    const int t = threadIdx.x;
#pragma unroll
    for (int i = t; i < Ee * Dd; i += 256) sW[i] = Wr2[i];
    __syncthreads();

    const int warp = t >> 5, lane = t & 31;
    const int tok = blockIdx.x * 8 + warp;

    float hv[8];
#pragma unroll
    for (int j = 0; j < 8; j++) hv[j] = g_h[(size_t)tok * Dd + j * 32 + lane];

    float lg[Ee];
#pragma unroll
    for (int e = 0; e < Ee; e++) {
        float s = 0.f;
#pragma unroll
        for (int j = 0; j < 8; j++) s += hv[j] * sW[e * Dd + j * 32 + lane];
#pragma unroll
        for (int o = 16; o; o >>= 1) s += __shfl_xor_sync(0xffffffffu, s, o);
        lg[e] = s;
    }

    if (lane == 0) {
        float v0 = -1e30f, v1 = -1e30f;
        int   i0 = 0, i1 = 0;
#pragma unroll
        for (int e = 0; e < Ee; e++) {
            const float v = lg[e] + br2[e];
            if (v > v0)      { v1 = v0; i1 = i0; v0 = v; i0 = e; }
            else if (v > v1) { v1 = v;  i1 = e; }
        }
        const float e1  = __expf(v1 - v0);
        const float inv = 1.f / (1.f + e1);
        g_prob[tok * 2 + 0] = inv;
        g_prob[tok * 2 + 1] = e1 * inv;
        const int p0 = atomicAdd(&g_cnt[i0], 1);
        g_list[0][i0 * Bsz + p0] = tok;
        const int p1 = atomicAdd(&g_cnt[16 + i1], 1);
        g_list[1][i1 * Bsz + p1] = tok;
    }
}

// ---------------------------------------------------------------------------
extern "C" void kernel_launch(void* const* d_in, const int* in_sizes, int n_in,
                              void* d_out, int out_size)
{
    (void)in_sizes; (void)n_in; (void)out_size;
    const float* x   = (const float*)d_in[0];
    const float* Wr1 = (const float*)d_in[1];
    const float* br1 = (const float*)d_in[2];
    const float* Wr2 = (const float*)d_in[3];
    const float* br2 = (const float*)d_in[4];
    const float* We  = (const float*)d_in[5];
    const float* be  = (const float*)d_in[6];
    float* out = (float*)d_out;

    static bool attr_done = false;
    if (!attr_done) {
        cudaFuncSetAttribute(gemm1_tf32x3_kernel,
                             cudaFuncAttributeMaxDynamicSharedMemorySize, SMEM1_BYTES);
        cudaFuncSetAttribute(gemm_bf16x3_kernel<1>,
                             cudaFuncAttributeMaxDynamicSharedMemorySize, SMEM2_BYTES);
        cudaFuncSetAttribute(gemm_bf16x3_kernel<2>,
                             cudaFuncAttributeMaxDynamicSharedMemorySize, SMEM2_BYTES);
        attr_done = true;
    }

    zero_cnt_kernel<<<1, 32>>>();

    // GEMM1: h = lrelu(x @ Wr1^T + br1)   (tf32x3: router flips need this)
    gemm1_tf32x3_kernel<<<dim3(Bsz / 128, Dd / 128, 1), 256, SMEM1_BYTES>>>(x, Wr1, br1);

    // Router stage 2 + top-2 + softmax + expert binning
    router_topk_kernel<<<Bsz / 8, 256>>>(Wr2, br2);

    // Expert pass, slot 0: out = p0 * (We[e0] @ x + be[e0])   (bf16x3)
    gemm_bf16x3_kernel<1><<<dim3(Bsz / 128, Dd / 128, Ee), 256, SMEM2_BYTES>>>(x, We, be, out);

    // Expert pass, slot 1: out = lrelu(out + p1 * (We[e1] @ x + be[e1]))   (bf16x3)
    gemm_bf16x3_kernel<2><<<dim3(Bsz / 128, Dd / 128, Ee), 256, SMEM2_BYTES>>>(x, We, be, out);
}